// round 12
// baseline (speedup 1.0000x reference)
#include <cuda_runtime.h>
#include <cstdint>

// Problem constants (fixed by the dataset: x [32,256,512], embeddings [8192,512])
#define N_TOK   8192
#define K_CODES 8192
#define DIM     512

// Argmin-GEMM tiling: persistent blocks (2 CTAs/SM), items = (mtile, split)
#define TM 128       // token rows per item
#define TN 128       // codes per k-chunk
#define TD 16        // D-slice per smem stage (small: duplicated x tile)
#define SPLITS 32    // K splits (item granularity for load balance)
#define KS (K_CODES / SPLITS)        // 256
#define NCHUNK (KS / TN)             // 2
#define NSTAGE (DIM / TD)            // 32
#define MTILES (N_TOK / TM)          // 64
#define ITEMS (MTILES * SPLITS)      // 2048
#define GRID_PERSIST 296             // 2 CTAs per SM x 148 SMs

#define XS_STRIDE (2 * TM + 2)       // 258 floats (even -> LDS.64 aligned)
#define ES_STRIDE (TN + 2)           // 130 floats

// ---------------- device scratch (no allocations allowed) ----------------
// Referenced ONLY from device code (host-side use of a __device__ symbol is the
// host shadow address -> UVM pool allocation -> harness mem-guard failure).
__device__ float g_esq[K_CODES];
__device__ float g_xsq[N_TOK];
__device__ float g_pval[SPLITS][N_TOK];
__device__ int   g_pidx[SPLITS][N_TOK];
__device__ float g_rowsq[N_TOK];

// ---------------- packed f32x2 helpers (sm_100a Blackwell) ----------------
// Each 32-bit lane of fma.rn.f32x2 is an independent IEEE fp32 FMA, so a packed
// accumulator chain over ascending d is bit-identical to a scalar FFMA chain.
__device__ __forceinline__ unsigned long long pack2(float a, float b) {
    unsigned long long r;
    asm("mov.b64 %0, {%1, %2};" : "=l"(r) : "f"(a), "f"(b));
    return r;
}
__device__ __forceinline__ void unpack2(unsigned long long v, float& a, float& b) {
    asm("mov.b64 {%0, %1}, %2;" : "=f"(a), "=f"(b) : "l"(v));
}
__device__ __forceinline__ unsigned long long fma2(unsigned long long a,
                                                   unsigned long long b,
                                                   unsigned long long c) {
    unsigned long long d;
    asm("fma.rn.f32x2 %0, %1, %2, %3;" : "=l"(d) : "l"(a), "l"(b), "l"(c));
    return d;
}

// ---------------- kernel 1a: e_sq[k] = sum_d E[k][d]^2 ----------------
// XLA row-reduce replica: lane-strided ascending accumulation, NON-FUSED
// mul+add, butterfly tree. (Verified bit-exact R9-R11.)
__global__ void vq_esq(const float* __restrict__ E) {
    int w = (blockIdx.x * blockDim.x + threadIdx.x) >> 5;
    int lane = threadIdx.x & 31;
    if (w >= K_CODES) return;
    const float* row = E + (size_t)w * DIM;
    float s = 0.f;
    #pragma unroll
    for (int d = lane; d < DIM; d += 32) {
        float v = __ldg(row + d);
        s = __fadd_rn(s, __fmul_rn(v, v));
    }
    #pragma unroll
    for (int o = 16; o > 0; o >>= 1) s = __fadd_rn(s, __shfl_xor_sync(0xffffffffu, s, o));
    if (lane == 0) g_esq[w] = s;
}

// ---------------- kernel 1b: x_sq[n] = sum_d x[n][d]^2 ----------------
__global__ void vq_xsq(const float* __restrict__ x) {
    int w = (blockIdx.x * blockDim.x + threadIdx.x) >> 5;
    int lane = threadIdx.x & 31;
    if (w >= N_TOK) return;
    const float* row = x + (size_t)w * DIM;
    float s = 0.f;
    #pragma unroll
    for (int d = lane; d < DIM; d += 32) {
        float v = __ldg(row + d);
        s = __fadd_rn(s, __fmul_rn(v, v));
    }
    #pragma unroll
    for (int o = 16; o > 0; o >>= 1) s = __fadd_rn(s, __shfl_xor_sync(0xffffffffu, s, o));
    if (lane == 0) g_xsq[w] = s;
}

// ---------------- kernel 2: persistent fused fp32-dot + argmin ----------------
// 296 blocks (2/SM) x 256 threads, round-robin over 2048 (mtile, split) items.
// Broadcast-x layout: xs_dup stores each x value twice, so LDS.64 gives (v,v).
// Thread tile 8 rows (ty + 16i) x 8 cols (32p + 2tx + {0,1}):
//   acc[i][p] = fma2((r_i, r_i), (c_even, c_odd), acc[i][p])
// Per d: 8 xb LDS.64 + 4 ep LDS.64 + 32 FFMA2 -- no swap MOVs.
// Every lane is a serial ascending-d fp32 FMA chain -> bit-identical.
// dist[n][k] = fl( fl(x_sq[n] - 2*dot) + e_sq[k] ), first-index tie-break.
__global__ __launch_bounds__(256, 2) void vq_argmin(const float* __restrict__ x,
                                                    const float* __restrict__ E) {
    __shared__ __align__(16) float xs_dup[TD][XS_STRIDE];  // 16.5 KB
    __shared__ __align__(16) float es[TD][ES_STRIDE];      //  8.3 KB

    const int t  = threadIdx.x;
    const int tx = t & 15;
    const int ty = t >> 4;
    const int lrow = t >> 1;           // loader row 0..127
    const int lp8  = (t & 1) * 8;      // loader d-offset (8 floats each)

    for (int item = blockIdx.x; item < ITEMS; item += GRID_PERSIST) {
        const int mtile = item >> 5;               // / SPLITS
        const int split = item & (SPLITS - 1);
        const int m0 = mtile * TM;
        const int kbase = split * KS;

        float xsqv[8];
        #pragma unroll
        for (int i = 0; i < 8; i++) xsqv[i] = g_xsq[m0 + ty + 16 * i];

        float bestv[8];
        int   besti[8];
        #pragma unroll
        for (int i = 0; i < 8; i++) { bestv[i] = 3.4e38f; besti[i] = 0; }

        const unsigned long long zero2 = pack2(0.f, 0.f);

        for (int c = 0; c < NCHUNK; c++) {
            const int k0 = kbase + c * TN;

            unsigned long long acc[8][4];
            #pragma unroll
            for (int i = 0; i < 8; i++)
                #pragma unroll
                for (int p = 0; p < 4; p++) acc[i][p] = zero2;

            for (int s = 0; s < NSTAGE; s++) {
                const int d0 = s * TD;
                __syncthreads();   // previous stage's readers done
                {   // x: row lrow, d-range [d0+lp8, +8), stored duplicated
                    const float* xp = &x[(size_t)(m0 + lrow) * DIM + d0 + lp8];
                    float4 a0 = *reinterpret_cast<const float4*>(xp);
                    float4 a1 = *reinterpret_cast<const float4*>(xp + 4);
                    unsigned long long* dst;
                    #define XDUP(j, v) \
                        dst = reinterpret_cast<unsigned long long*>(&xs_dup[lp8 + (j)][2 * lrow]); \
                        *dst = pack2((v), (v));
                    XDUP(0, a0.x) XDUP(1, a0.y) XDUP(2, a0.z) XDUP(3, a0.w)
                    XDUP(4, a1.x) XDUP(5, a1.y) XDUP(6, a1.z) XDUP(7, a1.w)
                    #undef XDUP
                    // e: row lrow, same d-range, plain transposed
                    const float* epg = &E[(size_t)(k0 + lrow) * DIM + d0 + lp8];
                    float4 b0 = *reinterpret_cast<const float4*>(epg);
                    float4 b1 = *reinterpret_cast<const float4*>(epg + 4);
                    es[lp8 + 0][lrow] = b0.x; es[lp8 + 1][lrow] = b0.y;
                    es[lp8 + 2][lrow] = b0.z; es[lp8 + 3][lrow] = b0.w;
                    es[lp8 + 4][lrow] = b1.x; es[lp8 + 5][lrow] = b1.y;
                    es[lp8 + 6][lrow] = b1.z; es[lp8 + 7][lrow] = b1.w;
                }
                __syncthreads();
                #pragma unroll
                for (int d = 0; d < TD; d++) {
                    unsigned long long ep[4];
                    #pragma unroll
                    for (int p = 0; p < 4; p++)
                        ep[p] = *reinterpret_cast<const unsigned long long*>(&es[d][32 * p + 2 * tx]);
                    #pragma unroll
                    for (int i = 0; i < 8; i++) {
                        unsigned long long xb =
                            *reinterpret_cast<const unsigned long long*>(&xs_dup[d][2 * (ty + 16 * i)]);
                        #pragma unroll
                        for (int p = 0; p < 4; p++)
                            acc[i][p] = fma2(xb, ep[p], acc[i][p]);
                    }
                }
            }

            // epilogue: dist = fl( fl(x_sq - 2*dot) + e_sq ); ascending k, strict <
            #pragma unroll
            for (int p = 0; p < 4; p++) {
                int c0 = k0 + 32 * p + 2 * tx;
                float eq0 = __ldg(&g_esq[c0]);
                float eq1 = __ldg(&g_esq[c0 + 1]);
                #pragma unroll
                for (int i = 0; i < 8; i++) {
                    float a0, a1;
                    unpack2(acc[i][p], a0, a1);      // (r_i*c0, r_i*c1)
                    float s0 = __fadd_rn(fmaf(-2.f, a0, xsqv[i]), eq0);
                    if (s0 < bestv[i]) { bestv[i] = s0; besti[i] = c0; }
                    float s1 = __fadd_rn(fmaf(-2.f, a1, xsqv[i]), eq1);
                    if (s1 < bestv[i]) { bestv[i] = s1; besti[i] = c0 + 1; }
                }
            }
        }

        // cross-thread reduction per item; alias dead tile buffers
        __syncthreads();
        float* rv = &xs_dup[0][0];                  // [TM][16] = 8 KB
        int*   ri = reinterpret_cast<int*>(&es[0][0]);
        #pragma unroll
        for (int i = 0; i < 8; i++) {
            int row = ty + 16 * i;
            rv[row * 16 + tx] = bestv[i];
            ri[row * 16 + tx] = besti[i];
        }
        __syncthreads();
        if (t < TM) {
            float bv = rv[t * 16];
            int   bi = ri[t * 16];
            #pragma unroll
            for (int j = 1; j < 16; j++) {
                float v = rv[t * 16 + j];
                int idx = ri[t * 16 + j];
                if (v < bv || (v == bv && idx < bi)) { bv = v; bi = idx; }
            }
            g_pval[split][m0 + t] = bv;
            g_pidx[split][m0 + t] = bi;
        }
        // next item's first __syncthreads() orders these reads vs buffer reuse
    }
}

// ---------------- kernel 3: combine splits, gather, write q_st + indices ----------------
__global__ void vq_combine(const float* __restrict__ x, const float* __restrict__ E,
                           float* __restrict__ out) {
    int gw   = (blockIdx.x * blockDim.x + threadIdx.x) >> 5;  // one warp per token row
    int lane = threadIdx.x & 31;
    if (gw >= N_TOK) return;

    float bv = g_pval[0][gw];
    int   bi = g_pidx[0][gw];
    #pragma unroll
    for (int s = 1; s < SPLITS; s++) {
        float v = g_pval[s][gw];
        int idx = g_pidx[s][gw];
        if (v < bv || (v == bv && idx < bi)) { bv = v; bi = idx; }
    }

    const float* er = E + (size_t)bi * DIM;
    const float* xr = x + (size_t)gw * DIM;
    float* qr = out + (size_t)gw * DIM;
    float sq = 0.f;
    #pragma unroll
    for (int d = lane; d < DIM; d += 32) {
        float e  = er[d];
        float xv = xr[d];
        qr[d] = __fadd_rn(xv, __fadd_rn(e, -xv));  // straight-through: fl(x + fl(q - x))
        float df = __fadd_rn(xv, -e);
        sq = __fadd_rn(sq, __fmul_rn(df, df));
    }
    #pragma unroll
    for (int o = 16; o > 0; o >>= 1) sq = __fadd_rn(sq, __shfl_xor_sync(0xffffffffu, sq, o));
    if (lane == 0) {
        g_rowsq[gw] = sq;
        out[(size_t)N_TOK * DIM + gw] = (float)bi;   // indices as float32
    }
}

// ---------------- kernel 4: deterministic loss reduction ----------------
__global__ void vq_loss(float* __restrict__ out) {
    __shared__ float red[256];
    int t = threadIdx.x;
    float s = 0.f;
    for (int i = t; i < N_TOK; i += 256) s += g_rowsq[i];
    red[t] = s;
    __syncthreads();
    #pragma unroll
    for (int o = 128; o > 0; o >>= 1) {
        if (t < o) red[t] += red[t + o];
        __syncthreads();
    }
    if (t == 0) {
        float mse = red[0] / (float)((size_t)N_TOK * DIM);
        size_t base = (size_t)N_TOK * DIM + N_TOK;
        out[base + 0] = 0.25f * mse;   // commitment_loss
        out[base + 1] = mse;           // codebook_loss
        out[base + 2] = 1.25f * mse;   // total_loss
    }
}

// ---------------- entry point ----------------
extern "C" void kernel_launch(void* const* d_in, const int* in_sizes, int n_in,
                              void* d_out, int out_size) {
    (void)in_sizes; (void)n_in; (void)out_size;
    const float* x = (const float*)d_in[0];   // [32*256, 512]
    const float* E = (const float*)d_in[1];   // [8192, 512]
    float* out = (float*)d_out;

    vq_esq<<<K_CODES * 32 / 256, 256>>>(E);
    vq_xsq<<<N_TOK * 32 / 256, 256>>>(x);
    vq_argmin<<<GRID_PERSIST, 256>>>(x, E);
    vq_combine<<<N_TOK * 32 / 256, 256>>>(x, E, out);
    vq_loss<<<1, 256>>>(out);
}

// round 13
// speedup vs baseline: 1.0078x; 1.0078x over previous
#include <cuda_runtime.h>
#include <cstdint>

// Problem constants (fixed by the dataset: x [32,256,512], embeddings [8192,512])
#define N_TOK   8192
#define K_CODES 8192
#define DIM     512

// Argmin-GEMM tiling: persistent blocks (2 CTAs/SM), items = (mtile, split)
#define TM 128       // token rows per item
#define TN 128       // codes per k-chunk
#define TD 32        // D-slice per smem stage (restored to R11 depth)
#define SPLITS 32    // K splits (item granularity for load balance)
#define KS (K_CODES / SPLITS)        // 256
#define NCHUNK (KS / TN)             // 2
#define NSTAGE (DIM / TD)            // 16
#define MTILES (N_TOK / TM)          // 64
#define ITEMS (MTILES * SPLITS)      // 2048
#define GRID_PERSIST 296             // 2 CTAs per SM x 148 SMs

#define XS_STRIDE (2 * TM + 2)       // 258 floats (even -> LDS.64 aligned)
#define ES_STRIDE (TN + 2)           // 130 floats
#define SMEM_FLOATS (TD * XS_STRIDE + TD * ES_STRIDE)   // 12416
#define SMEM_BYTES  (SMEM_FLOATS * 4)                   // 49664 (> 48KB static cap -> dynamic)

// ---------------- device scratch (no allocations allowed) ----------------
// Referenced ONLY from device code (host-side use of a __device__ symbol is the
// host shadow address -> UVM pool allocation -> harness mem-guard failure).
__device__ float g_esq[K_CODES];
__device__ float g_xsq[N_TOK];
__device__ float g_pval[SPLITS][N_TOK];
__device__ int   g_pidx[SPLITS][N_TOK];
__device__ float g_rowsq[N_TOK];

// ---------------- packed f32x2 helpers (sm_100a Blackwell) ----------------
// Each 32-bit lane of fma.rn.f32x2 is an independent IEEE fp32 FMA, so a packed
// accumulator chain over ascending d is bit-identical to a scalar FFMA chain.
__device__ __forceinline__ unsigned long long pack2(float a, float b) {
    unsigned long long r;
    asm("mov.b64 %0, {%1, %2};" : "=l"(r) : "f"(a), "f"(b));
    return r;
}
__device__ __forceinline__ void unpack2(unsigned long long v, float& a, float& b) {
    asm("mov.b64 {%0, %1}, %2;" : "=f"(a), "=f"(b) : "l"(v));
}
__device__ __forceinline__ unsigned long long fma2(unsigned long long a,
                                                   unsigned long long b,
                                                   unsigned long long c) {
    unsigned long long d;
    asm("fma.rn.f32x2 %0, %1, %2, %3;" : "=l"(d) : "l"(a), "l"(b), "l"(c));
    return d;
}

// ---------------- kernel 1a: e_sq[k] = sum_d E[k][d]^2 ----------------
// XLA row-reduce replica: lane-strided ascending accumulation, NON-FUSED
// mul+add, butterfly tree. (Verified bit-exact R9-R12.)
__global__ void vq_esq(const float* __restrict__ E) {
    int w = (blockIdx.x * blockDim.x + threadIdx.x) >> 5;
    int lane = threadIdx.x & 31;
    if (w >= K_CODES) return;
    const float* row = E + (size_t)w * DIM;
    float s = 0.f;
    #pragma unroll
    for (int d = lane; d < DIM; d += 32) {
        float v = __ldg(row + d);
        s = __fadd_rn(s, __fmul_rn(v, v));
    }
    #pragma unroll
    for (int o = 16; o > 0; o >>= 1) s = __fadd_rn(s, __shfl_xor_sync(0xffffffffu, s, o));
    if (lane == 0) g_esq[w] = s;
}

// ---------------- kernel 1b: x_sq[n] = sum_d x[n][d]^2 ----------------
__global__ void vq_xsq(const float* __restrict__ x) {
    int w = (blockIdx.x * blockDim.x + threadIdx.x) >> 5;
    int lane = threadIdx.x & 31;
    if (w >= N_TOK) return;
    const float* row = x + (size_t)w * DIM;
    float s = 0.f;
    #pragma unroll
    for (int d = lane; d < DIM; d += 32) {
        float v = __ldg(row + d);
        s = __fadd_rn(s, __fmul_rn(v, v));
    }
    #pragma unroll
    for (int o = 16; o > 0; o >>= 1) s = __fadd_rn(s, __shfl_xor_sync(0xffffffffu, s, o));
    if (lane == 0) g_xsq[w] = s;
}

// ---------------- kernel 2: persistent fused fp32-dot + argmin ----------------
// 296 blocks (2/SM) x 256 threads, round-robin over 2048 (mtile, split) items.
// Dynamic smem (49.7 KB/CTA): broadcast-x duplicated tile at full TD=32 depth.
// Thread tile 8 rows (ty + 16i) x 8 cols (32p + 2tx + {0,1}):
//   acc[i][p] = fma2((r_i, r_i), (c_even, c_odd), acc[i][p])
// Per d: 8 xb LDS.64 + 4 ep LDS.64 + 32 FFMA2 -- no swap MOVs.
// Every lane is a serial ascending-d fp32 FMA chain -> bit-identical.
// dist[n][k] = fl( fl(x_sq[n] - 2*dot) + e_sq[k] ), first-index tie-break.
__global__ __launch_bounds__(256, 2) void vq_argmin(const float* __restrict__ x,
                                                    const float* __restrict__ E) {
    extern __shared__ __align__(16) float smem[];
    float (*xs_dup)[XS_STRIDE] = reinterpret_cast<float(*)[XS_STRIDE]>(smem);
    float (*es)[ES_STRIDE] = reinterpret_cast<float(*)[ES_STRIDE]>(smem + TD * XS_STRIDE);

    const int t  = threadIdx.x;
    const int tx = t & 15;
    const int ty = t >> 4;
    const int lrow  = t >> 1;          // loader row 0..127
    const int lhalf = (t & 1) * 16;    // loader d-offset (16 floats each)

    for (int item = blockIdx.x; item < ITEMS; item += GRID_PERSIST) {
        const int mtile = item >> 5;               // / SPLITS
        const int split = item & (SPLITS - 1);
        const int m0 = mtile * TM;
        const int kbase = split * KS;

        float xsqv[8];
        #pragma unroll
        for (int i = 0; i < 8; i++) xsqv[i] = g_xsq[m0 + ty + 16 * i];

        float bestv[8];
        int   besti[8];
        #pragma unroll
        for (int i = 0; i < 8; i++) { bestv[i] = 3.4e38f; besti[i] = 0; }

        const unsigned long long zero2 = pack2(0.f, 0.f);

        for (int c = 0; c < NCHUNK; c++) {
            const int k0 = kbase + c * TN;

            unsigned long long acc[8][4];
            #pragma unroll
            for (int i = 0; i < 8; i++)
                #pragma unroll
                for (int p = 0; p < 4; p++) acc[i][p] = zero2;

            for (int s = 0; s < NSTAGE; s++) {
                const int d0 = s * TD;
                __syncthreads();   // previous stage's readers done
                {   // x: row lrow, 16 d-values, stored duplicated (v,v)
                    const float* xp = &x[(size_t)(m0 + lrow) * DIM + d0 + lhalf];
                    #pragma unroll
                    for (int v4 = 0; v4 < 4; v4++) {
                        float4 a = *reinterpret_cast<const float4*>(xp + 4 * v4);
                        unsigned long long* dst;
                        dst = reinterpret_cast<unsigned long long*>(&xs_dup[lhalf + 4 * v4 + 0][2 * lrow]);
                        *dst = pack2(a.x, a.x);
                        dst = reinterpret_cast<unsigned long long*>(&xs_dup[lhalf + 4 * v4 + 1][2 * lrow]);
                        *dst = pack2(a.y, a.y);
                        dst = reinterpret_cast<unsigned long long*>(&xs_dup[lhalf + 4 * v4 + 2][2 * lrow]);
                        *dst = pack2(a.z, a.z);
                        dst = reinterpret_cast<unsigned long long*>(&xs_dup[lhalf + 4 * v4 + 3][2 * lrow]);
                        *dst = pack2(a.w, a.w);
                    }
                    // e: row lrow, 16 d-values, plain transposed
                    const float* epg = &E[(size_t)(k0 + lrow) * DIM + d0 + lhalf];
                    #pragma unroll
                    for (int v4 = 0; v4 < 4; v4++) {
                        float4 b = *reinterpret_cast<const float4*>(epg + 4 * v4);
                        es[lhalf + 4 * v4 + 0][lrow] = b.x;
                        es[lhalf + 4 * v4 + 1][lrow] = b.y;
                        es[lhalf + 4 * v4 + 2][lrow] = b.z;
                        es[lhalf + 4 * v4 + 3][lrow] = b.w;
                    }
                }
                __syncthreads();
                #pragma unroll 8
                for (int d = 0; d < TD; d++) {
                    unsigned long long ep[4];
                    #pragma unroll
                    for (int p = 0; p < 4; p++)
                        ep[p] = *reinterpret_cast<const unsigned long long*>(&es[d][32 * p + 2 * tx]);
                    #pragma unroll
                    for (int i = 0; i < 8; i++) {
                        unsigned long long xb =
                            *reinterpret_cast<const unsigned long long*>(&xs_dup[d][2 * (ty + 16 * i)]);
                        #pragma unroll
                        for (int p = 0; p < 4; p++)
                            acc[i][p] = fma2(xb, ep[p], acc[i][p]);
                    }
                }
            }

            // epilogue: dist = fl( fl(x_sq - 2*dot) + e_sq ); ascending k, strict <
            #pragma unroll
            for (int p = 0; p < 4; p++) {
                int c0 = k0 + 32 * p + 2 * tx;
                float eq0 = __ldg(&g_esq[c0]);
                float eq1 = __ldg(&g_esq[c0 + 1]);
                #pragma unroll
                for (int i = 0; i < 8; i++) {
                    float a0, a1;
                    unpack2(acc[i][p], a0, a1);      // (r_i*c0, r_i*c1)
                    float s0 = __fadd_rn(fmaf(-2.f, a0, xsqv[i]), eq0);
                    if (s0 < bestv[i]) { bestv[i] = s0; besti[i] = c0; }
                    float s1 = __fadd_rn(fmaf(-2.f, a1, xsqv[i]), eq1);
                    if (s1 < bestv[i]) { bestv[i] = s1; besti[i] = c0 + 1; }
                }
            }
        }

        // cross-thread reduction per item; alias dead tile buffers
        __syncthreads();
        float* rv = smem;                                   // [TM][16] = 8 KB
        int*   ri = reinterpret_cast<int*>(smem + TM * 16); // [TM][16] = 8 KB
        #pragma unroll
        for (int i = 0; i < 8; i++) {
            int row = ty + 16 * i;
            rv[row * 16 + tx] = bestv[i];
            ri[row * 16 + tx] = besti[i];
        }
        __syncthreads();
        if (t < TM) {
            float bv = rv[t * 16];
            int   bi = ri[t * 16];
            #pragma unroll
            for (int j = 1; j < 16; j++) {
                float v = rv[t * 16 + j];
                int idx = ri[t * 16 + j];
                if (v < bv || (v == bv && idx < bi)) { bv = v; bi = idx; }
            }
            g_pval[split][m0 + t] = bv;
            g_pidx[split][m0 + t] = bi;
        }
        // next item's first __syncthreads() orders these reads vs buffer reuse
    }
}

// ---------------- kernel 3: combine splits, gather, write q_st + indices ----------------
__global__ void vq_combine(const float* __restrict__ x, const float* __restrict__ E,
                           float* __restrict__ out) {
    int gw   = (blockIdx.x * blockDim.x + threadIdx.x) >> 5;  // one warp per token row
    int lane = threadIdx.x & 31;
    if (gw >= N_TOK) return;

    float bv = g_pval[0][gw];
    int   bi = g_pidx[0][gw];
    #pragma unroll
    for (int s = 1; s < SPLITS; s++) {
        float v = g_pval[s][gw];
        int idx = g_pidx[s][gw];
        if (v < bv || (v == bv && idx < bi)) { bv = v; bi = idx; }
    }

    const float* er = E + (size_t)bi * DIM;
    const float* xr = x + (size_t)gw * DIM;
    float* qr = out + (size_t)gw * DIM;
    float sq = 0.f;
    #pragma unroll
    for (int d = lane; d < DIM; d += 32) {
        float e  = er[d];
        float xv = xr[d];
        qr[d] = __fadd_rn(xv, __fadd_rn(e, -xv));  // straight-through: fl(x + fl(q - x))
        float df = __fadd_rn(xv, -e);
        sq = __fadd_rn(sq, __fmul_rn(df, df));
    }
    #pragma unroll
    for (int o = 16; o > 0; o >>= 1) sq = __fadd_rn(sq, __shfl_xor_sync(0xffffffffu, sq, o));
    if (lane == 0) {
        g_rowsq[gw] = sq;
        out[(size_t)N_TOK * DIM + gw] = (float)bi;   // indices as float32
    }
}

// ---------------- kernel 4: deterministic loss reduction ----------------
__global__ void vq_loss(float* __restrict__ out) {
    __shared__ float red[256];
    int t = threadIdx.x;
    float s = 0.f;
    for (int i = t; i < N_TOK; i += 256) s += g_rowsq[i];
    red[t] = s;
    __syncthreads();
    #pragma unroll
    for (int o = 128; o > 0; o >>= 1) {
        if (t < o) red[t] += red[t + o];
        __syncthreads();
    }
    if (t == 0) {
        float mse = red[0] / (float)((size_t)N_TOK * DIM);
        size_t base = (size_t)N_TOK * DIM + N_TOK;
        out[base + 0] = 0.25f * mse;   // commitment_loss
        out[base + 1] = mse;           // codebook_loss
        out[base + 2] = 1.25f * mse;   // total_loss
    }
}

// ---------------- entry point ----------------
extern "C" void kernel_launch(void* const* d_in, const int* in_sizes, int n_in,
                              void* d_out, int out_size) {
    (void)in_sizes; (void)n_in; (void)out_size;
    const float* x = (const float*)d_in[0];   // [32*256, 512]
    const float* E = (const float*)d_in[1];   // [8192, 512]
    float* out = (float*)d_out;

    // Opt into >48KB dynamic smem (attribute set, not an allocation; idempotent,
    // executes immediately — not a captured stream op).
    cudaFuncSetAttribute(vq_argmin, cudaFuncAttributeMaxDynamicSharedMemorySize, SMEM_BYTES);

    vq_esq<<<K_CODES * 32 / 256, 256>>>(E);
    vq_xsq<<<N_TOK * 32 / 256, 256>>>(x);
    vq_argmin<<<GRID_PERSIST, 256, SMEM_BYTES>>>(x, E);
    vq_combine<<<N_TOK * 32 / 256, 256>>>(x, E, out);
    vq_loss<<<1, 256>>>(out);
}